// round 8
// baseline (speedup 1.0000x reference)
#include <cuda_runtime.h>
#include <math.h>

// ---------------------------------------------------------------------------
// SCRFD post-processing: decode -> sort(desc score) -> greedy NMS -> outputs
//
// Output layout (float32, 134400 elems):
//   [0      : 33600 )  boxes  (sorted, masked)  [8400,4]
//   [33600  : 42000 )  scores (sorted, masked)  [8400]
//   [42000  : 126000)  kps    (sorted, masked)  [8400,10]
//   [126000 : 134400)  keep   (0.0 / 1.0)       [8400]
// ---------------------------------------------------------------------------

#define NTOT 8400
#define NPAD 16384
#define KMAX 128
#define SCORE_T 0.5f
#define NMS_T   0.4f

__device__ float4        g_box[NTOT];        // decoded boxes (unsorted)
__device__ float         g_kps[NTOT * 10];   // decoded keypoints (unsorted)
__device__ float         g_key[NPAD];        // sort keys (sigmoid scores)
__device__ int           g_idx[NPAD];        // sort payload (orig index)
__device__ float4        g_sbox[NTOT];       // sorted boxes
__device__ float         g_area[NTOT];       // sorted areas
__device__ int           g_predcnt[NTOT];    // # predecessors with IoU>T
__device__ int           g_pred[NTOT * KMAX];
__device__ unsigned char g_keep[NTOT];

// ---------------------------------------------------------------------------
__global__ void decode_kernel(const float* __restrict__ s0, const float* __restrict__ b0, const float* __restrict__ k0,
                              const float* __restrict__ s1, const float* __restrict__ b1, const float* __restrict__ k1,
                              const float* __restrict__ s2, const float* __restrict__ b2, const float* __restrict__ k2)
{
    int n = blockIdx.x * blockDim.x + threadIdx.x;
    if (n >= NPAD) return;
    if (n >= NTOT) {                 // padding for power-of-2 bitonic sort
        g_key[n] = -1.0f;            // below any sigmoid value
        g_idx[n] = n;
        return;
    }
    const float *sp, *bp, *kp;
    int local, fw;
    float st;
    if (n < 6400)      { sp = s0; bp = b0; kp = k0; local = n;        fw = 80; st = 8.0f;  }
    else if (n < 8000) { sp = s1; bp = b1; kp = k1; local = n - 6400; fw = 40; st = 16.0f; }
    else               { sp = s2; bp = b2; kp = k2; local = n - 8000; fw = 20; st = 32.0f; }

    float px = (float)(local % fw) * st;   // exact (int*pow2)
    float py = (float)(local / fw) * st;

    // sigmoid in double: essentially correctly rounded => monotone ordering,
    // closest achievable match to JAX's score ordering.
    float x = sp[local];
    float s = (float)(1.0 / (1.0 + exp(-(double)x)));

    // strides are powers of two -> b*st exact -> decode bit-exact vs IEEE ref
    float4 bb;
    bb.x = px - bp[local * 4 + 0] * st;
    bb.y = py - bp[local * 4 + 1] * st;
    bb.z = px + bp[local * 4 + 2] * st;
    bb.w = py + bp[local * 4 + 3] * st;
    g_box[n] = bb;

#pragma unroll
    for (int q = 0; q < 10; q++) {
        float base = (q & 1) ? py : px;
        g_kps[n * 10 + q] = base + kp[local * 10 + q] * st;
    }

    g_key[n] = s;
    g_idx[n] = n;
    g_predcnt[n] = 0;   // fresh each graph replay
}

// ---------------------------------------------------------------------------
// Single-block bitonic sort on (key desc, idx asc). 16384 = 2^14 elements,
// global memory (L1/L2 resident), __syncthreads between steps.
__global__ void bitonic_kernel()
{
    for (int k = 2; k <= NPAD; k <<= 1) {
        for (int j = k >> 1; j > 0; j >>= 1) {
            for (int t = threadIdx.x; t < NPAD; t += blockDim.x) {
                int ixj = t ^ j;
                if (ixj > t) {
                    float a = g_key[t], b = g_key[ixj];
                    int   ia = g_idx[t], ib = g_idx[ixj];
                    bool aFirst = (a > b) || (a == b && ia < ib);   // desired order
                    bool desc   = ((t & k) == 0);                   // segment dir
                    if (desc ? !aFirst : aFirst) {
                        g_key[t] = b; g_key[ixj] = a;
                        g_idx[t] = ib; g_idx[ixj] = ia;
                    }
                }
            }
            __syncthreads();
        }
    }
}

// ---------------------------------------------------------------------------
__global__ void gather_kernel()
{
    int p = blockIdx.x * blockDim.x + threadIdx.x;
    if (p >= NTOT) return;
    int j = g_idx[p];
    float4 b = g_box[j];
    g_sbox[p] = b;
    // area = (x2-x1)*(y2-y1), exact IEEE ops (no contraction)
    g_area[p] = __fmul_rn(__fsub_rn(b.z, b.x), __fsub_rn(b.w, b.y));
}

// ---------------------------------------------------------------------------
// For each sorted item i, record predecessors j<i with IoU>NMS_T.
// IoU arithmetic replicates JAX bit-for-bit: explicit rn intrinsics block FMA
// contraction; division only when inter>0 (otherwise iou is 0 or NaN -> false).
__global__ void edge_kernel()
{
    int i = blockIdx.x;
    if (i == 0) return;
    float4 bi = g_sbox[i];
    float  ai = g_area[i];
    for (int j = threadIdx.x; j < i; j += blockDim.x) {
        float4 bj = g_sbox[j];
        float ltx = fmaxf(bi.x, bj.x);
        float lty = fmaxf(bi.y, bj.y);
        float rbx = fminf(bi.z, bj.z);
        float rby = fminf(bi.w, bj.w);
        float w = fmaxf(__fsub_rn(rbx, ltx), 0.0f);
        float h = fmaxf(__fsub_rn(rby, lty), 0.0f);
        float inter = __fmul_rn(w, h);
        if (inter > 0.0f) {
            float denom = __fadd_rn(__fsub_rn(__fadd_rn(ai, g_area[j]), inter), 1e-9f);
            float iou = __fdiv_rn(inter, denom);
            if (iou > NMS_T) {
                int pos = atomicAdd(&g_predcnt[i], 1);
                if (pos < KMAX) g_pred[i * KMAX + pos] = j;
            }
        }
    }
}

// ---------------------------------------------------------------------------
// Greedy NMS as a well-founded recurrence on the (sparse) predecessor DAG:
//   keep[i] = valid[i] && !any(pred j kept)
// Solved by chaotic in-place iteration in one block. Unique fixpoint on a DAG
// => "no change in a full round" implies exact result; the 8401-round cap
// guarantees exactness unconditionally (depth <= 8399).
__global__ void nms_kernel()
{
    __shared__ unsigned char keep[NTOT];
    __shared__ int wl[NTOT];
    __shared__ int wlcnt;
    __shared__ int changed;
    int tid = threadIdx.x;

    if (tid == 0) wlcnt = 0;
    __syncthreads();

    for (int p = tid; p < NTOT; p += blockDim.x) {
        bool valid = g_key[p] > SCORE_T;
        keep[p] = valid ? 1 : 0;
        if (valid && g_predcnt[p] > 0) {
            int w = atomicAdd(&wlcnt, 1);
            wl[w] = p;
        }
    }
    __syncthreads();
    int nw = wlcnt;

    for (int it = 0; it < 8401; it++) {
        if (tid == 0) changed = 0;
        __syncthreads();
        for (int w = tid; w < nw; w += blockDim.x) {
            int p = wl[w];
            int c = g_predcnt[p];
            if (c > KMAX) c = KMAX;
            const int* lst = &g_pred[p * KMAX];
            int any = 0;
            for (int e = 0; e < c; e++) any |= keep[lst[e]];
            unsigned char nv = any ? 0 : 1;
            if (nv != keep[p]) { keep[p] = nv; changed = 1; }
        }
        __syncthreads();
        int ch = changed;
        __syncthreads();
        if (!ch) break;
    }

    for (int p = tid; p < NTOT; p += blockDim.x) g_keep[p] = keep[p];
}

// ---------------------------------------------------------------------------
__global__ void output_kernel(float* __restrict__ out)
{
    int p = blockIdx.x * blockDim.x + threadIdx.x;
    if (p >= NTOT) return;
    float m = g_keep[p] ? 1.0f : 0.0f;
    float4 b = g_sbox[p];
    out[p * 4 + 0] = b.x * m;
    out[p * 4 + 1] = b.y * m;
    out[p * 4 + 2] = b.z * m;
    out[p * 4 + 3] = b.w * m;
    out[33600 + p] = g_key[p] * m;
    int j = g_idx[p];
#pragma unroll
    for (int q = 0; q < 10; q++)
        out[42000 + p * 10 + q] = g_kps[j * 10 + q] * m;
    out[126000 + p] = m;
}

// ---------------------------------------------------------------------------
extern "C" void kernel_launch(void* const* d_in, const int* in_sizes, int n_in,
                              void* d_out, int out_size)
{
    const float *s0, *b0, *k0, *s1, *b1, *k1, *s2, *b2, *k2;
    // Disambiguate metadata ordering at runtime:
    //   dict-insertion order: score0,bbox0,kps0,score1,... -> in_sizes[1]==25600
    //   signature order:      score0,score1,score2,bbox0,... -> in_sizes[1]==1600
    if (n_in >= 9 && in_sizes[1] == 25600) {
        s0 = (const float*)d_in[0]; b0 = (const float*)d_in[1]; k0 = (const float*)d_in[2];
        s1 = (const float*)d_in[3]; b1 = (const float*)d_in[4]; k1 = (const float*)d_in[5];
        s2 = (const float*)d_in[6]; b2 = (const float*)d_in[7]; k2 = (const float*)d_in[8];
    } else {
        s0 = (const float*)d_in[0]; s1 = (const float*)d_in[1]; s2 = (const float*)d_in[2];
        b0 = (const float*)d_in[3]; b1 = (const float*)d_in[4]; b2 = (const float*)d_in[5];
        k0 = (const float*)d_in[6]; k1 = (const float*)d_in[7]; k2 = (const float*)d_in[8];
    }

    decode_kernel<<<NPAD / 256, 256>>>(s0, b0, k0, s1, b1, k1, s2, b2, k2);
    bitonic_kernel<<<1, 1024>>>();
    gather_kernel<<<(NTOT + 255) / 256, 256>>>();
    edge_kernel<<<NTOT, 128>>>();
    nms_kernel<<<1, 1024>>>();
    output_kernel<<<(NTOT + 255) / 256, 256>>>((float*)d_out);
}

// round 9
// speedup vs baseline: 8.3019x; 8.3019x over previous
#include <cuda_runtime.h>
#include <math.h>

// ---------------------------------------------------------------------------
// SCRFD post-processing: decode -> rank-by-counting (exact stable argsort)
//                        -> sparse greedy NMS -> masked outputs
//
// Output layout (float32, 134400 elems):
//   [0      : 33600 )  boxes  (sorted, masked)  [8400,4]
//   [33600  : 42000 )  scores (sorted, masked)  [8400]
//   [42000  : 126000)  kps    (sorted, masked)  [8400,10]
//   [126000 : 134400)  keep   (0.0 / 1.0)       [8400]
// ---------------------------------------------------------------------------

#define NTOT 8400
#define KMAX 128
#define SCORE_T 0.5f
#define NMS_T   0.4f

// rank kernel geometry
#define RBLK 64            // elements ranked per block
#define RSEG 8             // segments the key stream is split into
#define RSEGLEN (NTOT / RSEG)   // 1050
#define RTHREADS (RBLK * RSEG)  // 512

typedef unsigned long long u64;
typedef unsigned int u32;

__device__ float4        g_box[NTOT];        // decoded boxes (orig order)
__device__ float         g_kps[NTOT * 10];   // decoded keypoints (orig order)
__device__ u64           g_pack[NTOT];       // (orderedKey<<32)|~idx
__device__ float         g_skey[NTOT];       // sorted scores
__device__ int           g_sidx[NTOT];       // sorted -> orig index
__device__ float4        g_sbox[NTOT];       // sorted boxes
__device__ float         g_area[NTOT];       // sorted areas
__device__ int           g_predcnt[NTOT];    // # predecessors with IoU>T
__device__ int           g_pred[NTOT * KMAX];
__device__ unsigned char g_keep[NTOT];

// ---------------------------------------------------------------------------
__global__ void decode_kernel(const float* __restrict__ s0, const float* __restrict__ b0, const float* __restrict__ k0,
                              const float* __restrict__ s1, const float* __restrict__ b1, const float* __restrict__ k1,
                              const float* __restrict__ s2, const float* __restrict__ b2, const float* __restrict__ k2)
{
    int n = blockIdx.x * blockDim.x + threadIdx.x;
    if (n >= NTOT) return;

    const float *sp, *bp, *kp;
    int local, fw;
    float st;
    if (n < 6400)      { sp = s0; bp = b0; kp = k0; local = n;        fw = 80; st = 8.0f;  }
    else if (n < 8000) { sp = s1; bp = b1; kp = k1; local = n - 6400; fw = 40; st = 16.0f; }
    else               { sp = s2; bp = b2; kp = k2; local = n - 8000; fw = 20; st = 32.0f; }

    float px = (float)(local % fw) * st;   // exact (int * pow2)
    float py = (float)(local / fw) * st;

    // sigmoid in double: essentially correctly rounded -> monotone ordering,
    // matches JAX's score ordering (verified rel_err 4e-8 in R7).
    float x = sp[local];
    float s = (float)(1.0 / (1.0 + exp(-(double)x)));

    // strides are powers of two -> b*st exact -> decode bit-exact vs IEEE ref
    float4 bb;
    bb.x = px - bp[local * 4 + 0] * st;
    bb.y = py - bp[local * 4 + 1] * st;
    bb.z = px + bp[local * 4 + 2] * st;
    bb.w = py + bp[local * 4 + 3] * st;
    g_box[n] = bb;

#pragma unroll
    for (int q = 0; q < 10; q++) {
        float base = (q & 1) ? py : px;
        g_kps[n * 10 + q] = base + kp[local * 10 + q] * st;
    }

    // strict total order: (score desc, idx asc). sigmoid > 0 -> sign bit clear,
    // XOR 0x80000000 makes the uint order match float order.
    u32 okey = __float_as_uint(s) ^ 0x80000000u;
    g_pack[n] = ((u64)okey << 32) | (u32)(~n);
    g_predcnt[n] = 0;   // fresh each graph replay
}

// ---------------------------------------------------------------------------
// Exact stable argsort via rank-by-counting: rank(i) = #{ j : pack[j] > pack[i] }.
// Strict total order -> ranks are a permutation -> direct scatter, no sort.
// 70.6M u64 compares spread over 132 blocks; keys smem-resident, warp-broadcast
// reads (all lanes of a warp share the same segment -> conflict-free).
__global__ void rank_kernel()
{
    extern __shared__ u64 sk[];              // NTOT u64 = 67.2 KB
    __shared__ int part[RSEG][RBLK];

    int tid = threadIdx.x;
    for (int t = tid; t < NTOT; t += RTHREADS)
        sk[t] = g_pack[t];
    __syncthreads();

    int el  = tid & (RBLK - 1);
    int seg = tid >> 6;                      // log2(RBLK)
    int i = blockIdx.x * RBLK + el;

    int cnt = 0;
    if (i < NTOT) {
        u64 ki = sk[i];
        int j0 = seg * RSEGLEN;
        int j1 = j0 + RSEGLEN;
#pragma unroll 4
        for (int j = j0; j < j1; j++)
            cnt += (sk[j] > ki) ? 1 : 0;
    }
    part[seg][el] = cnt;
    __syncthreads();

    if (seg == 0 && i < NTOT) {
        int rank = 0;
#pragma unroll
        for (int q = 0; q < RSEG; q++) rank += part[q][el];

        u32 okey = (u32)(sk[i] >> 32);
        float key = __uint_as_float(okey ^ 0x80000000u);
        float4 b = g_box[i];
        g_skey[rank] = key;
        g_sidx[rank] = i;
        g_sbox[rank] = b;
        g_area[rank] = __fmul_rn(__fsub_rn(b.z, b.x), __fsub_rn(b.w, b.y));
    }
}

// ---------------------------------------------------------------------------
// Predecessor lists for sorted item i: j<i with IoU>NMS_T. Only valid items
// (score > SCORE_T) can keep or suppress; sorted-descending makes validity a
// prefix, so invalid i are skipped entirely (and then all j<i are valid).
// IoU arithmetic replicates JAX bit-for-bit (rn intrinsics block contraction).
__global__ void edge_kernel()
{
    int i = blockIdx.x;
    if (i == 0) return;
    if (g_skey[i] <= SCORE_T) return;        // invalid prefix-pruned
    float4 bi = g_sbox[i];
    float  ai = g_area[i];
    for (int j = threadIdx.x; j < i; j += blockDim.x) {
        float4 bj = g_sbox[j];
        float ltx = fmaxf(bi.x, bj.x);
        float lty = fmaxf(bi.y, bj.y);
        float rbx = fminf(bi.z, bj.z);
        float rby = fminf(bi.w, bj.w);
        float w = fmaxf(__fsub_rn(rbx, ltx), 0.0f);
        float h = fmaxf(__fsub_rn(rby, lty), 0.0f);
        float inter = __fmul_rn(w, h);
        if (inter > 0.0f) {
            float denom = __fadd_rn(__fsub_rn(__fadd_rn(ai, g_area[j]), inter), 1e-9f);
            float iou = __fdiv_rn(inter, denom);
            if (iou > NMS_T) {
                int pos = atomicAdd(&g_predcnt[i], 1);
                if (pos < KMAX) g_pred[i * KMAX + pos] = j;
            }
        }
    }
}

// ---------------------------------------------------------------------------
// Greedy NMS as a well-founded recurrence on the sparse predecessor DAG:
//   keep[i] = valid[i] && !any(pred j kept)
// chaotic in-place iteration; unique fixpoint on a DAG -> "no change" = exact.
__global__ void nms_kernel()
{
    __shared__ unsigned char keep[NTOT];
    __shared__ int wl[NTOT];
    __shared__ int wlcnt;
    __shared__ int changed;
    int tid = threadIdx.x;

    if (tid == 0) wlcnt = 0;
    __syncthreads();

    for (int p = tid; p < NTOT; p += blockDim.x) {
        bool valid = g_skey[p] > SCORE_T;
        keep[p] = valid ? 1 : 0;
        if (valid && g_predcnt[p] > 0) {
            int w = atomicAdd(&wlcnt, 1);
            wl[w] = p;
        }
    }
    __syncthreads();
    int nw = wlcnt;

    for (int it = 0; it < NTOT + 1; it++) {
        if (tid == 0) changed = 0;
        __syncthreads();
        for (int w = tid; w < nw; w += blockDim.x) {
            int p = wl[w];
            int c = g_predcnt[p];
            if (c > KMAX) c = KMAX;
            const int* lst = &g_pred[p * KMAX];
            int any = 0;
            for (int e = 0; e < c; e++) any |= keep[lst[e]];
            unsigned char nv = any ? 0 : 1;
            if (nv != keep[p]) { keep[p] = nv; changed = 1; }
        }
        __syncthreads();
        int ch = changed;
        __syncthreads();
        if (!ch) break;
    }

    for (int p = tid; p < NTOT; p += blockDim.x) g_keep[p] = keep[p];
}

// ---------------------------------------------------------------------------
__global__ void output_kernel(float* __restrict__ out)
{
    int p = blockIdx.x * blockDim.x + threadIdx.x;
    if (p >= NTOT) return;
    float m = g_keep[p] ? 1.0f : 0.0f;
    float4 b = g_sbox[p];
    out[p * 4 + 0] = b.x * m;
    out[p * 4 + 1] = b.y * m;
    out[p * 4 + 2] = b.z * m;
    out[p * 4 + 3] = b.w * m;
    out[33600 + p] = g_skey[p] * m;
    int j = g_sidx[p];
#pragma unroll
    for (int q = 0; q < 10; q++)
        out[42000 + p * 10 + q] = g_kps[j * 10 + q] * m;
    out[126000 + p] = m;
}

// ---------------------------------------------------------------------------
extern "C" void kernel_launch(void* const* d_in, const int* in_sizes, int n_in,
                              void* d_out, int out_size)
{
    const float *s0, *b0, *k0, *s1, *b1, *k1, *s2, *b2, *k2;
    // dict-insertion order (score0,bbox0,kps0,...) vs signature order
    if (n_in >= 9 && in_sizes[1] == 25600) {
        s0 = (const float*)d_in[0]; b0 = (const float*)d_in[1]; k0 = (const float*)d_in[2];
        s1 = (const float*)d_in[3]; b1 = (const float*)d_in[4]; k1 = (const float*)d_in[5];
        s2 = (const float*)d_in[6]; b2 = (const float*)d_in[7]; k2 = (const float*)d_in[8];
    } else {
        s0 = (const float*)d_in[0]; s1 = (const float*)d_in[1]; s2 = (const float*)d_in[2];
        b0 = (const float*)d_in[3]; b1 = (const float*)d_in[4]; b2 = (const float*)d_in[5];
        k0 = (const float*)d_in[6]; k1 = (const float*)d_in[7]; k2 = (const float*)d_in[8];
    }

    static const size_t rank_smem = (size_t)NTOT * sizeof(u64);   // 67.2 KB
    cudaFuncSetAttribute(rank_kernel, cudaFuncAttributeMaxDynamicSharedMemorySize,
                         (int)rank_smem);   // immediate API, idempotent, not a stream op

    decode_kernel<<<(NTOT + 255) / 256, 256>>>(s0, b0, k0, s1, b1, k1, s2, b2, k2);
    rank_kernel<<<(NTOT + RBLK - 1) / RBLK, RTHREADS, rank_smem>>>();
    edge_kernel<<<NTOT, 128>>>();
    nms_kernel<<<1, 1024>>>();
    output_kernel<<<(NTOT + 255) / 256, 256>>>((float*)d_out);
}